// round 1
// baseline (speedup 1.0000x reference)
#include <cuda_runtime.h>
#include <math.h>

#define NN 50000
#define EE 640000
#define ET 690000   // EE + NN self loops

// ---------------- scratch (device globals; no allocation allowed) ----------
__device__ float     g_xl1[(size_t)NN * 256];
__device__ float     g_xr1[(size_t)NN * 256];
__device__ float     g_out1[(size_t)NN * 256];     // accum, then h = elu(...) in place
__device__ float     g_alpha1[(size_t)ET * 8];
__device__ unsigned  g_max1[NN * 8];
__device__ float     g_den1[NN * 8];
__device__ float     g_xl2[NN * 16];
__device__ float     g_xr2[NN * 16];
__device__ float     g_alpha2[ET];
__device__ unsigned  g_max2[NN];
__device__ float     g_den2[NN];

// ---------------- helpers ---------------------------------------------------
__device__ __forceinline__ int esrc(const int* ei, int e) { return e < EE ? ei[e] : e - EE; }
__device__ __forceinline__ int edst(const int* ei, int e) { return e < EE ? ei[EE + e] : e - EE; }

// order-preserving float<->uint encoding for atomicMax
__device__ __forceinline__ unsigned fenc(float f) {
    unsigned u = __float_as_uint(f);
    return (u & 0x80000000u) ? ~u : (u | 0x80000000u);
}
__device__ __forceinline__ float fdec(unsigned u) {
    return (u & 0x80000000u) ? __uint_as_float(u ^ 0x80000000u) : __uint_as_float(~u);
}

// ---------------- init ------------------------------------------------------
__global__ void k_init(float* __restrict__ dout) {
    int idx = blockIdx.x * 256 + threadIdx.x;
    if (idx < NN * 256) g_out1[idx] = 0.f;
    if (idx < NN * 16)  dout[idx] = 0.f;
    if (idx < NN * 8)   { g_max1[idx] = 0u; g_den1[idx] = 0.f; }
    if (idx < NN)       { g_max2[idx] = 0u; g_den2[idx] = 0.f; }
}

// ---------------- GEMM1: X[NN,128] @ [W1l | W1r][128,512] -------------------
__global__ void k_gemm1(const float* __restrict__ X,
                        const float* __restrict__ Wl,
                        const float* __restrict__ Wr) {
    __shared__ float As[16][64];   // [k][m]
    __shared__ float Bs[16][64];   // [k][n]
    const int bm = blockIdx.y * 64;
    const int bn = blockIdx.x * 64;
    const int tid = threadIdx.x;
    const int tx = tid & 15, ty = tid >> 4;

    float acc[4][4];
#pragma unroll
    for (int i = 0; i < 4; i++)
#pragma unroll
        for (int j = 0; j < 4; j++) acc[i][j] = 0.f;

    for (int k0 = 0; k0 < 128; k0 += 16) {
#pragma unroll
        for (int i = 0; i < 4; i++) {
            int idx = tid + i * 256;           // 0..1023
            int r = idx >> 4, c = idx & 15;    // r: 0..63, c: 0..15
            int row = bm + r;
            As[c][r] = (row < NN) ? X[row * 128 + k0 + c] : 0.f;
        }
#pragma unroll
        for (int i = 0; i < 4; i++) {
            int idx = tid + i * 256;
            int r = idx >> 6, c = idx & 63;    // r: 0..15, c: 0..63
            int col = bn + c, kk = k0 + r;
            Bs[r][c] = (col < 256) ? Wl[kk * 256 + col] : Wr[kk * 256 + col - 256];
        }
        __syncthreads();
#pragma unroll
        for (int k = 0; k < 16; k++) {
            float a[4], b[4];
#pragma unroll
            for (int i = 0; i < 4; i++) a[i] = As[k][ty * 4 + i];
#pragma unroll
            for (int j = 0; j < 4; j++) b[j] = Bs[k][tx * 4 + j];
#pragma unroll
            for (int i = 0; i < 4; i++)
#pragma unroll
                for (int j = 0; j < 4; j++) acc[i][j] += a[i] * b[j];
        }
        __syncthreads();
    }
#pragma unroll
    for (int i = 0; i < 4; i++) {
        int row = bm + ty * 4 + i;
        if (row >= NN) continue;
#pragma unroll
        for (int j = 0; j < 4; j++) {
            int col = bn + tx * 4 + j;
            float v = acc[i][j];
            if (col < 256) g_xl1[(size_t)row * 256 + col] = v;
            else           g_xr1[(size_t)row * 256 + col - 256] = v;
        }
    }
}

// ---------------- layer-1 edge scoring + segment max ------------------------
__global__ void k_score1(const int* __restrict__ ei, const float* __restrict__ att1) {
    int tid = blockIdx.x * 256 + threadIdx.x;
    if (tid >= ET * 8) return;
    int e = tid >> 3, h = tid & 7;
    int s = esrc(ei, e), d = edst(ei, e);
    const float* xl = g_xl1 + (size_t)s * 256 + h * 32;
    const float* xr = g_xr1 + (size_t)d * 256 + h * 32;
    const float* a  = att1 + h * 32;
    float sc = 0.f;
#pragma unroll
    for (int f = 0; f < 32; f++) {
        float v = xl[f] + xr[f];
        v = v > 0.f ? v : 0.2f * v;
        sc += v * a[f];
    }
    g_alpha1[(size_t)e * 8 + h] = sc;
    atomicMax(&g_max1[d * 8 + h], fenc(sc));
}

// ---------------- layer-1 exp + segment denom --------------------------------
__global__ void k_exp1(const int* __restrict__ ei) {
    int tid = blockIdx.x * 256 + threadIdx.x;
    if (tid >= ET * 8) return;
    int e = tid >> 3, h = tid & 7;
    int d = edst(ei, e);
    float m = fdec(g_max1[d * 8 + h]);
    float w = __expf(g_alpha1[tid] - m);
    g_alpha1[tid] = w;
    atomicAdd(&g_den1[d * 8 + h], w);
}

// ---------------- layer-1 aggregation (atomic scatter) -----------------------
__global__ void k_agg1(const int* __restrict__ ei) {
    int e = blockIdx.x;
    int c = threadIdx.x;        // 0..255
    int h = c >> 5;
    int s = esrc(ei, e), d = edst(ei, e);
    float w = g_alpha1[(size_t)e * 8 + h] / (g_den1[d * 8 + h] + 1e-16f);
    atomicAdd(&g_out1[(size_t)d * 256 + c], g_xl1[(size_t)s * 256 + c] * w);
}

// ---------------- ELU (+ b1) -------------------------------------------------
__global__ void k_elu(const float* __restrict__ b1) {
    int idx = blockIdx.x * 256 + threadIdx.x;
    if (idx >= NN * 256) return;
    float v = g_out1[idx] + b1[idx & 255];
    g_out1[idx] = v > 0.f ? v : expm1f(v);
}

// ---------------- GEMM2: h[NN,256] @ [W2l | W2r][256,32] --------------------
__global__ void k_gemm2(const float* __restrict__ Wl, const float* __restrict__ Wr) {
    __shared__ float ws[256 * 32];
    __shared__ float hs[8][256];
    int tid = threadIdx.x;
    for (int i = tid; i < 256 * 32; i += 256) {
        int k = i >> 5, c = i & 31;
        ws[i] = (c < 16) ? Wl[k * 16 + c] : Wr[k * 16 + c - 16];
    }
    int node0 = blockIdx.x * 8;
    for (int i = tid; i < 8 * 256; i += 256) {
        int m = i >> 8, k = i & 255;
        int node = node0 + m;
        hs[m][k] = (node < NN) ? g_out1[(size_t)node * 256 + k] : 0.f;
    }
    __syncthreads();
    int m = tid >> 5, c = tid & 31;
    int node = node0 + m;
    if (node < NN) {
        float sacc = 0.f;
#pragma unroll 8
        for (int k = 0; k < 256; k++) sacc += hs[m][k] * ws[k * 32 + c];
        if (c < 16) g_xl2[node * 16 + c] = sacc;
        else        g_xr2[node * 16 + c - 16] = sacc;
    }
}

// ---------------- layer-2 scoring + max --------------------------------------
__global__ void k_score2(const int* __restrict__ ei, const float* __restrict__ att2) {
    int e = blockIdx.x * 256 + threadIdx.x;
    if (e >= ET) return;
    int s = esrc(ei, e), d = edst(ei, e);
    float sc = 0.f;
#pragma unroll
    for (int f = 0; f < 16; f++) {
        float v = g_xl2[s * 16 + f] + g_xr2[d * 16 + f];
        v = v > 0.f ? v : 0.2f * v;
        sc += v * att2[f];
    }
    g_alpha2[e] = sc;
    atomicMax(&g_max2[d], fenc(sc));
}

__global__ void k_exp2(const int* __restrict__ ei) {
    int e = blockIdx.x * 256 + threadIdx.x;
    if (e >= ET) return;
    int d = edst(ei, e);
    float w = __expf(g_alpha2[e] - fdec(g_max2[d]));
    g_alpha2[e] = w;
    atomicAdd(&g_den2[d], w);
}

// ---------------- layer-2 aggregation ----------------------------------------
__global__ void k_agg2(const int* __restrict__ ei, float* __restrict__ dout) {
    int tid = blockIdx.x * 256 + threadIdx.x;
    if (tid >= ET * 16) return;
    int e = tid >> 4, f = tid & 15;
    int s = esrc(ei, e), d = edst(ei, e);
    float w = g_alpha2[e] / (g_den2[d] + 1e-16f);
    atomicAdd(&dout[d * 16 + f], g_xl2[s * 16 + f] * w);
}

// ---------------- final: + b2, leaky_relu(0.01) -------------------------------
__global__ void k_final(float* __restrict__ dout, const float* __restrict__ b2) {
    int idx = blockIdx.x * 256 + threadIdx.x;
    if (idx >= NN * 16) return;
    float v = dout[idx] + b2[idx & 15];
    dout[idx] = v >= 0.f ? v : 0.01f * v;
}

// ---------------- launch ------------------------------------------------------
extern "C" void kernel_launch(void* const* d_in, const int* in_sizes, int n_in,
                              void* d_out, int out_size) {
    const float* x    = (const float*)d_in[0];
    const int*   ei   = (const int*)d_in[1];
    const float* W1l  = (const float*)d_in[2];
    const float* W1r  = (const float*)d_in[3];
    const float* att1 = (const float*)d_in[4];
    const float* b1   = (const float*)d_in[5];
    const float* W2l  = (const float*)d_in[6];
    const float* W2r  = (const float*)d_in[7];
    const float* att2 = (const float*)d_in[8];
    const float* b2   = (const float*)d_in[9];
    float* out = (float*)d_out;

    k_init<<<(NN * 256 + 255) / 256, 256>>>(out);

    dim3 g1(8, (NN + 63) / 64);
    k_gemm1<<<g1, 256>>>(x, W1l, W1r);

    int t1 = ET * 8;
    k_score1<<<(t1 + 255) / 256, 256>>>(ei, att1);
    k_exp1<<<(t1 + 255) / 256, 256>>>(ei);
    k_agg1<<<ET, 256>>>(ei);

    k_elu<<<(NN * 256 + 255) / 256, 256>>>(b1);

    k_gemm2<<<(NN + 7) / 8, 256>>>(W2l, W2r);

    k_score2<<<(ET + 255) / 256, 256>>>(ei, att2);
    k_exp2<<<(ET + 255) / 256, 256>>>(ei);
    k_agg2<<<(ET * 16 + 255) / 256, 256>>>(ei, out);
    k_final<<<(NN * 16 + 255) / 256, 256>>>(out, b2);
}

// round 2
// speedup vs baseline: 3.2194x; 3.2194x over previous
#include <cuda_runtime.h>
#include <math.h>

#define NN 50000
#define EE 640000
#define ET 690000   // EE + NN self loops

// ---------------- scratch (device globals) ----------------------------------
__device__ float g_xl1[(size_t)NN * 256];
__device__ float g_xr1[(size_t)NN * 256];
__device__ float g_out1[(size_t)NN * 256];
__device__ float g_alpha1[(size_t)ET * 8];
__device__ float g_den1[NN * 8];
__device__ float g_xl2[NN * 16];
__device__ float g_xr2[NN * 16];
__device__ float g_alpha2[ET];
__device__ float g_den2[NN];
__device__ int   g_deg[NN];
__device__ int   g_start[NN + 1];
__device__ int   g_cursor[NN];
__device__ int   g_csr_src[ET];
__device__ int   g_csr_dst[ET];

// ---------------- CSR construction ------------------------------------------
__global__ void k_init() {
    int i = blockIdx.x * 256 + threadIdx.x;
    if (i < NN) { g_deg[i] = 0; g_cursor[i] = 0; }
}

__global__ void k_hist(const int* __restrict__ ei) {
    int e = blockIdx.x * 256 + threadIdx.x;
    if (e >= ET) return;
    int d = (e < EE) ? ei[EE + e] : e - EE;
    atomicAdd(&g_deg[d], 1);
}

__global__ void k_scan() {
    __shared__ int sums[1024];
    int t = threadIdx.x;
    const int C = 49;                 // 49*1024 = 50176 >= NN
    int base = t * C;
    int s = 0;
    for (int i = 0; i < C; i++) { int idx = base + i; if (idx < NN) s += g_deg[idx]; }
    sums[t] = s;
    __syncthreads();
    for (int off = 1; off < 1024; off <<= 1) {
        int v = 0;
        if (t >= off) v = sums[t - off];
        __syncthreads();
        sums[t] += v;
        __syncthreads();
    }
    int run = (t == 0) ? 0 : sums[t - 1];
    for (int i = 0; i < C; i++) {
        int idx = base + i;
        if (idx < NN) { g_start[idx] = run; run += g_deg[idx]; }
    }
    if (t == 1023) g_start[NN] = ET;
}

__global__ void k_scatter(const int* __restrict__ ei) {
    int e = blockIdx.x * 256 + threadIdx.x;
    if (e >= ET) return;
    int s = (e < EE) ? ei[e] : e - EE;
    int d = (e < EE) ? ei[EE + e] : e - EE;
    int p = g_start[d] + atomicAdd(&g_cursor[d], 1);
    g_csr_src[p] = s;
    g_csr_dst[p] = d;
}

// ---------------- GEMM1: X[NN,128] @ [W1l | W1r][128,512] -------------------
__global__ void k_gemm1(const float* __restrict__ X,
                        const float* __restrict__ Wl,
                        const float* __restrict__ Wr) {
    __shared__ float As[16][64];
    __shared__ float Bs[16][64];
    const int bm = blockIdx.y * 64;
    const int bn = blockIdx.x * 64;
    const int tid = threadIdx.x;
    const int tx = tid & 15, ty = tid >> 4;

    float acc[4][4];
#pragma unroll
    for (int i = 0; i < 4; i++)
#pragma unroll
        for (int j = 0; j < 4; j++) acc[i][j] = 0.f;

    for (int k0 = 0; k0 < 128; k0 += 16) {
#pragma unroll
        for (int i = 0; i < 4; i++) {
            int idx = tid + i * 256;
            int r = idx >> 4, c = idx & 15;
            int row = bm + r;
            As[c][r] = (row < NN) ? X[row * 128 + k0 + c] : 0.f;
        }
#pragma unroll
        for (int i = 0; i < 4; i++) {
            int idx = tid + i * 256;
            int r = idx >> 6, c = idx & 63;
            int col = bn + c, kk = k0 + r;
            Bs[r][c] = (col < 256) ? Wl[kk * 256 + col] : Wr[kk * 256 + col - 256];
        }
        __syncthreads();
#pragma unroll
        for (int k = 0; k < 16; k++) {
            float a[4], b[4];
#pragma unroll
            for (int i = 0; i < 4; i++) a[i] = As[k][ty * 4 + i];
#pragma unroll
            for (int j = 0; j < 4; j++) b[j] = Bs[k][tx * 4 + j];
#pragma unroll
            for (int i = 0; i < 4; i++)
#pragma unroll
                for (int j = 0; j < 4; j++) acc[i][j] += a[i] * b[j];
        }
        __syncthreads();
    }
#pragma unroll
    for (int i = 0; i < 4; i++) {
        int row = bm + ty * 4 + i;
        if (row >= NN) continue;
#pragma unroll
        for (int j = 0; j < 4; j++) {
            int col = bn + tx * 4 + j;
            float v = acc[i][j];
            if (col < 256) g_xl1[(size_t)row * 256 + col] = v;
            else           g_xr1[(size_t)row * 256 + col - 256] = v;
        }
    }
}

// ---------------- layer-1 edge scoring (warp per CSR position) ---------------
__global__ void k_score1(const float* __restrict__ att1) {
    __shared__ float s_att[256];
    int t = threadIdx.x;
    s_att[t] = att1[t];
    __syncthreads();
    int p = blockIdx.x * 8 + (t >> 5);
    if (p >= ET) return;
    int lane = t & 31;
    int s = g_csr_src[p], d = g_csr_dst[p];
    const float* xl = g_xl1 + (size_t)s * 256;
    const float* xr = g_xr1 + (size_t)d * 256;
    float acc[8];
#pragma unroll
    for (int h = 0; h < 8; h++) {
        float v = xl[h * 32 + lane] + xr[h * 32 + lane];
        v = v > 0.f ? v : 0.2f * v;
        acc[h] = v * s_att[h * 32 + lane];
    }
#pragma unroll
    for (int h = 0; h < 8; h++)
#pragma unroll
        for (int o = 16; o; o >>= 1) acc[h] += __shfl_xor_sync(0xFFFFFFFFu, acc[h], o);
    if (lane < 8) {
        float out = acc[0];
#pragma unroll
        for (int h = 1; h < 8; h++) if (lane == h) out = acc[h];
        g_alpha1[(size_t)p * 8 + lane] = out;
    }
}

// ---------------- layer-1 segment softmax (warp per node) --------------------
__global__ void k_softmax1() {
    int node = blockIdx.x * 8 + (threadIdx.x >> 5);
    if (node >= NN) return;
    int lane = threadIdx.x & 31;
    int p0 = g_start[node], p1 = g_start[node + 1];
    float m[8];
#pragma unroll
    for (int h = 0; h < 8; h++) m[h] = -1e30f;
    for (int p = p0 + lane; p < p1; p += 32) {
        const float* a = g_alpha1 + (size_t)p * 8;
#pragma unroll
        for (int h = 0; h < 8; h++) m[h] = fmaxf(m[h], a[h]);
    }
#pragma unroll
    for (int h = 0; h < 8; h++)
#pragma unroll
        for (int o = 16; o; o >>= 1) m[h] = fmaxf(m[h], __shfl_xor_sync(0xFFFFFFFFu, m[h], o));
    float den[8];
#pragma unroll
    for (int h = 0; h < 8; h++) den[h] = 0.f;
    for (int p = p0 + lane; p < p1; p += 32) {
        float* a = g_alpha1 + (size_t)p * 8;
#pragma unroll
        for (int h = 0; h < 8; h++) {
            float w = __expf(a[h] - m[h]);
            a[h] = w;
            den[h] += w;
        }
    }
#pragma unroll
    for (int h = 0; h < 8; h++)
#pragma unroll
        for (int o = 16; o; o >>= 1) den[h] += __shfl_xor_sync(0xFFFFFFFFu, den[h], o);
    if (lane < 8) {
        float out = den[0];
#pragma unroll
        for (int h = 1; h < 8; h++) if (lane == h) out = den[h];
        g_den1[node * 8 + lane] = out;
    }
}

// ---------------- layer-1 aggregation (warp per node, +b1, ELU) --------------
__global__ void k_agg1(const float* __restrict__ b1) {
    int node = blockIdx.x * 8 + (threadIdx.x >> 5);
    if (node >= NN) return;
    int lane = threadIdx.x & 31;
    int p0 = g_start[node], p1 = g_start[node + 1];
    float acc[8];
#pragma unroll
    for (int h = 0; h < 8; h++) acc[h] = 0.f;
    for (int p = p0; p < p1; p++) {
        int s = g_csr_src[p];
        const float* a  = g_alpha1 + (size_t)p * 8;
        const float* xl = g_xl1 + (size_t)s * 256;
#pragma unroll
        for (int h = 0; h < 8; h++)
            acc[h] += xl[h * 32 + lane] * a[h];
    }
#pragma unroll
    for (int h = 0; h < 8; h++) {
        float den = g_den1[node * 8 + h];
        float v = acc[h] / (den + 1e-16f) + b1[h * 32 + lane];
        g_out1[(size_t)node * 256 + h * 32 + lane] = v > 0.f ? v : expm1f(v);
    }
}

// ---------------- GEMM2: h[NN,256] @ [W2l | W2r][256,32] --------------------
__global__ void k_gemm2(const float* __restrict__ Wl, const float* __restrict__ Wr) {
    __shared__ float ws[256 * 32];
    __shared__ float hs[8][256];
    int tid = threadIdx.x;
    for (int i = tid; i < 256 * 32; i += 256) {
        int k = i >> 5, c = i & 31;
        ws[i] = (c < 16) ? Wl[k * 16 + c] : Wr[k * 16 + c - 16];
    }
    int node0 = blockIdx.x * 8;
    for (int i = tid; i < 8 * 256; i += 256) {
        int m = i >> 8, k = i & 255;
        int node = node0 + m;
        hs[m][k] = (node < NN) ? g_out1[(size_t)node * 256 + k] : 0.f;
    }
    __syncthreads();
    int m = tid >> 5, c = tid & 31;
    int node = node0 + m;
    if (node < NN) {
        float sacc = 0.f;
#pragma unroll 8
        for (int k = 0; k < 256; k++) sacc += hs[m][k] * ws[k * 32 + c];
        if (c < 16) g_xl2[node * 16 + c] = sacc;
        else        g_xr2[node * 16 + c - 16] = sacc;
    }
}

// ---------------- layer-2 scoring (thread per CSR position) ------------------
__global__ void k_score2(const float* __restrict__ att2) {
    int p = blockIdx.x * 256 + threadIdx.x;
    if (p >= ET) return;
    int s = g_csr_src[p], d = g_csr_dst[p];
    const float* xl = g_xl2 + s * 16;
    const float* xr = g_xr2 + d * 16;
    float acc = 0.f;
#pragma unroll
    for (int f = 0; f < 16; f++) {
        float v = xl[f] + xr[f];
        v = v > 0.f ? v : 0.2f * v;
        acc += v * att2[f];
    }
    g_alpha2[p] = acc;
}

// ---------------- layer-2 segment softmax (warp per node) --------------------
__global__ void k_softmax2() {
    int node = blockIdx.x * 8 + (threadIdx.x >> 5);
    if (node >= NN) return;
    int lane = threadIdx.x & 31;
    int p0 = g_start[node], p1 = g_start[node + 1];
    float m = -1e30f;
    for (int p = p0 + lane; p < p1; p += 32) m = fmaxf(m, g_alpha2[p]);
#pragma unroll
    for (int o = 16; o; o >>= 1) m = fmaxf(m, __shfl_xor_sync(0xFFFFFFFFu, m, o));
    float den = 0.f;
    for (int p = p0 + lane; p < p1; p += 32) {
        float w = __expf(g_alpha2[p] - m);
        g_alpha2[p] = w;
        den += w;
    }
#pragma unroll
    for (int o = 16; o; o >>= 1) den += __shfl_xor_sync(0xFFFFFFFFu, den, o);
    if (lane == 0) g_den2[node] = den;
}

// ---------------- layer-2 aggregation (16 threads/node, +b2, leaky) ----------
__global__ void k_agg2(float* __restrict__ dout, const float* __restrict__ b2) {
    int tid = blockIdx.x * 256 + threadIdx.x;
    int node = tid >> 4;
    if (node >= NN) return;
    int c = tid & 15;
    int p0 = g_start[node], p1 = g_start[node + 1];
    float acc = 0.f;
    for (int p = p0; p < p1; p++) {
        int s = g_csr_src[p];
        acc += g_xl2[s * 16 + c] * g_alpha2[p];
    }
    float v = acc / (g_den2[node] + 1e-16f) + b2[c];
    dout[node * 16 + c] = v >= 0.f ? v : 0.01f * v;
}

// ---------------- launch ------------------------------------------------------
extern "C" void kernel_launch(void* const* d_in, const int* in_sizes, int n_in,
                              void* d_out, int out_size) {
    const float* x    = (const float*)d_in[0];
    const int*   ei   = (const int*)d_in[1];
    const float* W1l  = (const float*)d_in[2];
    const float* W1r  = (const float*)d_in[3];
    const float* att1 = (const float*)d_in[4];
    const float* b1   = (const float*)d_in[5];
    const float* W2l  = (const float*)d_in[6];
    const float* W2r  = (const float*)d_in[7];
    const float* att2 = (const float*)d_in[8];
    const float* b2   = (const float*)d_in[9];
    float* out = (float*)d_out;

    k_init<<<(NN + 255) / 256, 256>>>();
    k_hist<<<(ET + 255) / 256, 256>>>(ei);
    k_scan<<<1, 1024>>>();
    k_scatter<<<(ET + 255) / 256, 256>>>(ei);

    dim3 g1(8, (NN + 63) / 64);
    k_gemm1<<<g1, 256>>>(x, W1l, W1r);

    k_score1<<<(ET + 7) / 8, 256>>>(att1);
    k_softmax1<<<(NN + 7) / 8, 256>>>();
    k_agg1<<<(NN + 7) / 8, 256>>>(b1);

    k_gemm2<<<(NN + 7) / 8, 256>>>(W2l, W2r);

    k_score2<<<(ET + 255) / 256, 256>>>(att2);
    k_softmax2<<<(NN + 7) / 8, 256>>>();
    k_agg2<<<(NN * 16 + 255) / 256, 256>>>(out, b2);
}

// round 3
// speedup vs baseline: 3.5038x; 1.0884x over previous
#include <cuda_runtime.h>
#include <math.h>

#define NN 50000
#define EE 640000
#define ET 690000   // EE + NN self loops

// ---------------- scratch (device globals) ----------------------------------
__device__ float g_xl1[(size_t)NN * 256];
__device__ float g_xr1[(size_t)NN * 256];
__device__ float g_out1[(size_t)NN * 256];
__device__ float g_xl2[NN * 16];
__device__ float g_xr2[NN * 16];
__device__ int   g_deg[NN];
__device__ int   g_start[NN + 1];
__device__ int   g_cursor[NN];
__device__ int   g_csr_src[ET];

// ---------------- CSR construction ------------------------------------------
__global__ void k_init() {
    int i = blockIdx.x * 256 + threadIdx.x;
    if (i < NN) { g_deg[i] = 0; g_cursor[i] = 0; }
}

__global__ void k_hist(const int* __restrict__ ei) {
    int e = blockIdx.x * 256 + threadIdx.x;
    if (e >= ET) return;
    int d = (e < EE) ? ei[EE + e] : e - EE;
    atomicAdd(&g_deg[d], 1);
}

__global__ void k_scan() {
    __shared__ int sums[1024];
    int t = threadIdx.x;
    const int C = 49;                 // 49*1024 = 50176 >= NN
    int base = t * C;
    int s = 0;
    for (int i = 0; i < C; i++) { int idx = base + i; if (idx < NN) s += g_deg[idx]; }
    sums[t] = s;
    __syncthreads();
    for (int off = 1; off < 1024; off <<= 1) {
        int v = 0;
        if (t >= off) v = sums[t - off];
        __syncthreads();
        sums[t] += v;
        __syncthreads();
    }
    int run = (t == 0) ? 0 : sums[t - 1];
    for (int i = 0; i < C; i++) {
        int idx = base + i;
        if (idx < NN) { g_start[idx] = run; run += g_deg[idx]; }
    }
    if (t == 1023) g_start[NN] = ET;
}

__global__ void k_scatter(const int* __restrict__ ei) {
    int e = blockIdx.x * 256 + threadIdx.x;
    if (e >= ET) return;
    int s = (e < EE) ? ei[e] : e - EE;
    int d = (e < EE) ? ei[EE + e] : e - EE;
    int p = g_start[d] + atomicAdd(&g_cursor[d], 1);
    g_csr_src[p] = s;
}

// ---------------- GEMM1: X[NN,128] @ [W1l | W1r][128,512] -------------------
// 128x128 tile, BK=8, 256 threads, 8x8 micro-tile.
__global__ void __launch_bounds__(256, 2) k_gemm1(const float* __restrict__ X,
                                                  const float* __restrict__ Wl,
                                                  const float* __restrict__ Wr) {
    __shared__ float As[8][128];
    __shared__ float Bs[8][128];
    const int bm = blockIdx.y * 128;
    const int bn = blockIdx.x * 128;            // 0,128,256,384
    const int tid = threadIdx.x;
    const int tx = tid & 15, ty = tid >> 4;

    const float* Bsrc = (bn < 256) ? Wl : Wr;
    const int bn_loc = (bn < 256) ? bn : bn - 256;

    // A load mapping: thread loads float4 at row (tid>>1), cols (tid&1)*4
    const int arow = tid >> 1, acol = (tid & 1) * 4;
    // B load mapping: row tid>>5 (0..7), cols (tid&31)*4
    const int brow = tid >> 5, bcol = (tid & 31) * 4;

    float acc[8][8];
#pragma unroll
    for (int i = 0; i < 8; i++)
#pragma unroll
        for (int j = 0; j < 8; j++) acc[i][j] = 0.f;

    for (int k0 = 0; k0 < 128; k0 += 8) {
        float4 av = make_float4(0.f, 0.f, 0.f, 0.f);
        if (bm + arow < NN)
            av = *(const float4*)(X + (size_t)(bm + arow) * 128 + k0 + acol);
        As[acol + 0][arow] = av.x;
        As[acol + 1][arow] = av.y;
        As[acol + 2][arow] = av.z;
        As[acol + 3][arow] = av.w;
        *(float4*)&Bs[brow][bcol] =
            *(const float4*)(Bsrc + (size_t)(k0 + brow) * 256 + bn_loc + bcol);
        __syncthreads();
#pragma unroll
        for (int k = 0; k < 8; k++) {
            float a[8], b[8];
#pragma unroll
            for (int i = 0; i < 8; i++) a[i] = As[k][ty * 8 + i];
#pragma unroll
            for (int j = 0; j < 8; j++) b[j] = Bs[k][tx * 8 + j];
#pragma unroll
            for (int i = 0; i < 8; i++)
#pragma unroll
                for (int j = 0; j < 8; j++) acc[i][j] += a[i] * b[j];
        }
        __syncthreads();
    }

    float* dst_base = (bn < 256) ? g_xl1 : g_xr1;
#pragma unroll
    for (int i = 0; i < 8; i++) {
        int row = bm + ty * 8 + i;
        if (row >= NN) continue;
        float* drow = dst_base + (size_t)row * 256 + ((bn < 256) ? bn : bn - 256) + tx * 8;
        *(float4*)(drow)     = make_float4(acc[i][0], acc[i][1], acc[i][2], acc[i][3]);
        *(float4*)(drow + 4) = make_float4(acc[i][4], acc[i][5], acc[i][6], acc[i][7]);
    }
}

// ---------------- layer-1 fused: score + online softmax + aggregate + ELU ----
__global__ void k_fused1(const float* __restrict__ att1, const float* __restrict__ b1) {
    __shared__ float s_att[256];
    __shared__ float s_b[256];
    int t = threadIdx.x;
    s_att[t] = att1[t];
    s_b[t] = b1[t];
    __syncthreads();

    int node = blockIdx.x * 8 + (t >> 5);
    if (node >= NN) return;
    int lane = t & 31;
    int p0 = g_start[node], p1 = g_start[node + 1];

    float xr[8], att[8], m[8], den[8], acc[8];
#pragma unroll
    for (int h = 0; h < 8; h++) {
        xr[h]  = g_xr1[(size_t)node * 256 + h * 32 + lane];
        att[h] = s_att[h * 32 + lane];
        m[h] = -1e30f; den[h] = 0.f; acc[h] = 0.f;
    }

    for (int p = p0; p < p1; p++) {
        int s = g_csr_src[p];
        const float* xlrow = g_xl1 + (size_t)s * 256;
        float xl[8], sc[8];
#pragma unroll
        for (int h = 0; h < 8; h++) xl[h] = xlrow[h * 32 + lane];
#pragma unroll
        for (int h = 0; h < 8; h++) {
            float v = xl[h] + xr[h];
            v = v > 0.f ? v : 0.2f * v;
            sc[h] = v * att[h];
        }
        // butterfly reduce: all lanes end with the full per-head score
#pragma unroll
        for (int h = 0; h < 8; h++)
#pragma unroll
            for (int o = 16; o; o >>= 1) sc[h] += __shfl_xor_sync(0xFFFFFFFFu, sc[h], o);
        // online softmax update (branch is warp-uniform: sc, m identical on all lanes)
#pragma unroll
        for (int h = 0; h < 8; h++) {
            if (sc[h] <= m[h]) {
                float w = __expf(sc[h] - m[h]);
                den[h] += w;
                acc[h] += w * xl[h];
            } else {
                float scale = __expf(m[h] - sc[h]);
                den[h] = den[h] * scale + 1.f;
                acc[h] = acc[h] * scale + xl[h];
                m[h] = sc[h];
            }
        }
    }
#pragma unroll
    for (int h = 0; h < 8; h++) {
        float v = acc[h] / (den[h] + 1e-16f) + s_b[h * 32 + lane];
        g_out1[(size_t)node * 256 + h * 32 + lane] = v > 0.f ? v : expm1f(v);
    }
}

// ---------------- GEMM2: h[NN,256] @ [W2l | W2r][256,32] --------------------
__global__ void k_gemm2(const float* __restrict__ Wl, const float* __restrict__ Wr) {
    __shared__ float ws[256 * 32];
    __shared__ float hs[8][256];
    int tid = threadIdx.x;
    for (int i = tid; i < 256 * 32; i += 256) {
        int k = i >> 5, c = i & 31;
        ws[i] = (c < 16) ? Wl[k * 16 + c] : Wr[k * 16 + c - 16];
    }
    int node0 = blockIdx.x * 8;
    for (int i = tid; i < 8 * 256; i += 256) {
        int m = i >> 8, k = i & 255;
        int node = node0 + m;
        hs[m][k] = (node < NN) ? g_out1[(size_t)node * 256 + k] : 0.f;
    }
    __syncthreads();
    int m = tid >> 5, c = tid & 31;
    int node = node0 + m;
    if (node < NN) {
        float sacc = 0.f;
#pragma unroll 8
        for (int k = 0; k < 256; k++) sacc += hs[m][k] * ws[k * 32 + c];
        if (c < 16) g_xl2[node * 16 + c] = sacc;
        else        g_xr2[node * 16 + c - 16] = sacc;
    }
}

// ---------------- layer-2 fused: score + online softmax + agg + bias + leaky -
__global__ void k_fused2(const float* __restrict__ att2, const float* __restrict__ b2,
                         float* __restrict__ dout) {
    int t = threadIdx.x;
    int node = blockIdx.x * 8 + (t >> 5);
    if (node >= NN) return;
    int lane = t & 31;
    int c = lane & 15;
    int p0 = g_start[node], p1 = g_start[node + 1];

    float xr = g_xr2[node * 16 + c];
    float at = att2[c];
    float m = -1e30f, den = 0.f, acc = 0.f;

    for (int p = p0; p < p1; p++) {
        int s = g_csr_src[p];
        float xl = g_xl2[s * 16 + c];
        float v = xl + xr;
        v = v > 0.f ? v : 0.2f * v;
        float sc = v * at;
        // reduce over the 16-lane group (both halves compute identically)
#pragma unroll
        for (int o = 8; o; o >>= 1) sc += __shfl_xor_sync(0xFFFFFFFFu, sc, o);
        if (sc <= m) {
            float w = __expf(sc - m);
            den += w;
            acc += w * xl;
        } else {
            float scale = __expf(m - sc);
            den = den * scale + 1.f;
            acc = acc * scale + xl;
            m = sc;
        }
    }
    if (lane < 16) {
        float v = acc / (den + 1e-16f) + b2[c];
        dout[node * 16 + c] = v >= 0.f ? v : 0.01f * v;
    }
}

// ---------------- launch ------------------------------------------------------
extern "C" void kernel_launch(void* const* d_in, const int* in_sizes, int n_in,
                              void* d_out, int out_size) {
    const float* x    = (const float*)d_in[0];
    const int*   ei   = (const int*)d_in[1];
    const float* W1l  = (const float*)d_in[2];
    const float* W1r  = (const float*)d_in[3];
    const float* att1 = (const float*)d_in[4];
    const float* b1   = (const float*)d_in[5];
    const float* W2l  = (const float*)d_in[6];
    const float* W2r  = (const float*)d_in[7];
    const float* att2 = (const float*)d_in[8];
    const float* b2   = (const float*)d_in[9];
    float* out = (float*)d_out;

    k_init<<<(NN + 255) / 256, 256>>>();
    k_hist<<<(ET + 255) / 256, 256>>>(ei);
    k_scan<<<1, 1024>>>();
    k_scatter<<<(ET + 255) / 256, 256>>>(ei);

    dim3 g1(4, (NN + 127) / 128);
    k_gemm1<<<g1, 256>>>(x, W1l, W1r);

    k_fused1<<<(NN + 7) / 8, 256>>>(att1, b1);

    k_gemm2<<<(NN + 7) / 8, 256>>>(W2l, W2r);

    k_fused2<<<(NN + 7) / 8, 256>>>(att2, b2, out);
}

// round 4
// speedup vs baseline: 4.2169x; 1.2035x over previous
#include <cuda_runtime.h>
#include <math.h>
#include <stdint.h>

#define NN 50000
#define EE 640000
#define ET 690000   // EE + NN self loops

// ---------------- scratch (device globals) ----------------------------------
__device__ float g_xl1[(size_t)NN * 256];
__device__ float g_xr1[(size_t)NN * 256];
__device__ float g_out1[(size_t)NN * 256];
__device__ float g_alpha1[(size_t)ET * 8];
__device__ float g_xl2[NN * 16];
__device__ float g_xr2[NN * 16];
__device__ int   g_deg[NN];
__device__ int   g_start[NN + 1];
__device__ int   g_cursor[NN];
__device__ int   g_csr_src[ET];
__device__ int   g_csr_dst[ET];

// ---------------- CSR construction ------------------------------------------
__global__ void k_init() {
    int i = blockIdx.x * 256 + threadIdx.x;
    if (i < NN) { g_deg[i] = 0; g_cursor[i] = 0; }
}

__global__ void k_hist(const int* __restrict__ ei) {
    int e = blockIdx.x * 256 + threadIdx.x;
    if (e >= ET) return;
    int d = (e < EE) ? ei[EE + e] : e - EE;
    atomicAdd(&g_deg[d], 1);
}

__global__ void k_scan() {
    __shared__ int sums[1024];
    int t = threadIdx.x;
    const int C = 49;                 // 49*1024 = 50176 >= NN
    int base = t * C;
    int s = 0;
    for (int i = 0; i < C; i++) { int idx = base + i; if (idx < NN) s += g_deg[idx]; }
    sums[t] = s;
    __syncthreads();
    for (int off = 1; off < 1024; off <<= 1) {
        int v = 0;
        if (t >= off) v = sums[t - off];
        __syncthreads();
        sums[t] += v;
        __syncthreads();
    }
    int run = (t == 0) ? 0 : sums[t - 1];
    for (int i = 0; i < C; i++) {
        int idx = base + i;
        if (idx < NN) { g_start[idx] = run; run += g_deg[idx]; }
    }
    if (t == 1023) g_start[NN] = ET;
}

__global__ void k_scatter(const int* __restrict__ ei) {
    int e = blockIdx.x * 256 + threadIdx.x;
    if (e >= ET) return;
    int s = (e < EE) ? ei[e] : e - EE;
    int d = (e < EE) ? ei[EE + e] : e - EE;
    int p = g_start[d] + atomicAdd(&g_cursor[d], 1);
    g_csr_src[p] = s;
    g_csr_dst[p] = d;
}

// ---------------- tf32 helpers ------------------------------------------------
__device__ __forceinline__ float tf32r(float x) {
    uint32_t o;
    asm("cvt.rna.tf32.f32 %0, %1;" : "=r"(o) : "f"(x));
    return __uint_as_float(o);
}

__device__ __forceinline__ void mma_tf32(float c[4], const uint32_t a[4], const uint32_t b[2]) {
    asm volatile(
        "mma.sync.aligned.m16n8k8.row.col.f32.tf32.tf32.f32 "
        "{%0,%1,%2,%3},{%4,%5,%6,%7},{%8,%9},{%0,%1,%2,%3};"
        : "+f"(c[0]), "+f"(c[1]), "+f"(c[2]), "+f"(c[3])
        : "r"(a[0]), "r"(a[1]), "r"(a[2]), "r"(a[3]), "r"(b[0]), "r"(b[1]));
}

// ---------------- GEMM1 (tf32 tensor core): X[NN,128] @ [W1l|W1r][128,512] ---
// 128x128 block tile, BK=32, 256 threads = 8 warps (2m x 4n), warp = 64x32.
#define LDA 137
#define LDB 136
__global__ void __launch_bounds__(256, 2) k_gemm1(const float* __restrict__ X,
                                                  const float* __restrict__ Wl,
                                                  const float* __restrict__ Wr) {
    __shared__ float As[32 * LDA];   // [k][m], tf32-rounded
    __shared__ float Bs[32 * LDB];   // [k][n], tf32-rounded
    const int bm = blockIdx.y * 128;
    const int bn = blockIdx.x * 128;             // 0,128,256,384
    const float* Bsrc = (bn < 256) ? Wl : Wr;
    const int bnl = bn & 255;                    // local col base within Wl/Wr

    const int tid = threadIdx.x;
    const int wid = tid >> 5, lane = tid & 31;
    const int wm = wid >> 2, wn = wid & 3;
    const int g = lane >> 2, tg = lane & 3;

    float acc[4][4][4];
#pragma unroll
    for (int mt = 0; mt < 4; mt++)
#pragma unroll
        for (int nt = 0; nt < 4; nt++)
#pragma unroll
            for (int r = 0; r < 4; r++) acc[mt][nt][r] = 0.f;

    for (int k0 = 0; k0 < 128; k0 += 32) {
        // stage A: As[k][m] = tf32(X[bm+m][k0+k]); coalesced loads, conflict-free STS
#pragma unroll
        for (int it = 0; it < 4; it++) {
            int idx = tid + it * 256;            // 0..1023
            int m = idx >> 3, kq = (idx & 7) * 4;
            float4 v = make_float4(0.f, 0.f, 0.f, 0.f);
            int row = bm + m;
            if (row < NN) v = *(const float4*)(X + (size_t)row * 128 + k0 + kq);
            As[(kq + 0) * LDA + m] = tf32r(v.x);
            As[(kq + 1) * LDA + m] = tf32r(v.y);
            As[(kq + 2) * LDA + m] = tf32r(v.z);
            As[(kq + 3) * LDA + m] = tf32r(v.w);
        }
        // stage B: Bs[k][n] = tf32(W[k0+k][bnl+n]); coalesced
#pragma unroll
        for (int it = 0; it < 4; it++) {
            int idx = tid + it * 256;
            int k = idx >> 5, nf = (idx & 31) * 4;
            float4 v = *(const float4*)(Bsrc + (size_t)(k0 + k) * 256 + bnl + nf);
            Bs[k * LDB + nf + 0] = tf32r(v.x);
            Bs[k * LDB + nf + 1] = tf32r(v.y);
            Bs[k * LDB + nf + 2] = tf32r(v.z);
            Bs[k * LDB + nf + 3] = tf32r(v.w);
        }
        __syncthreads();

#pragma unroll
        for (int ks = 0; ks < 4; ks++) {
            int kk = ks * 8;
            uint32_t a[4][4], b[4][2];
#pragma unroll
            for (int mt = 0; mt < 4; mt++) {
                int rb = wm * 64 + mt * 16 + g;
                a[mt][0] = __float_as_uint(As[(kk + tg) * LDA + rb]);
                a[mt][1] = __float_as_uint(As[(kk + tg) * LDA + rb + 8]);
                a[mt][2] = __float_as_uint(As[(kk + tg + 4) * LDA + rb]);
                a[mt][3] = __float_as_uint(As[(kk + tg + 4) * LDA + rb + 8]);
            }
#pragma unroll
            for (int nt = 0; nt < 4; nt++) {
                int cb = wn * 32 + nt * 8 + g;
                b[nt][0] = __float_as_uint(Bs[(kk + tg) * LDB + cb]);
                b[nt][1] = __float_as_uint(Bs[(kk + tg + 4) * LDB + cb]);
            }
#pragma unroll
            for (int mt = 0; mt < 4; mt++)
#pragma unroll
                for (int nt = 0; nt < 4; nt++)
                    mma_tf32(acc[mt][nt], a[mt], b[nt]);
        }
        __syncthreads();
    }

    // epilogue
    float* dst = (bn < 256) ? g_xl1 : g_xr1;
#pragma unroll
    for (int mt = 0; mt < 4; mt++) {
        int row0 = bm + wm * 64 + mt * 16 + g;
#pragma unroll
        for (int nt = 0; nt < 4; nt++) {
            int col = bnl + wn * 32 + nt * 8 + 2 * tg;
            if (row0 < NN)
                *(float2*)(dst + (size_t)row0 * 256 + col) =
                    make_float2(acc[mt][nt][0], acc[mt][nt][1]);
            if (row0 + 8 < NN)
                *(float2*)(dst + (size_t)(row0 + 8) * 256 + col) =
                    make_float2(acc[mt][nt][2], acc[mt][nt][3]);
        }
    }
}

// ---------------- layer-1 edge scoring (warp per CSR position) ---------------
__global__ void k_score1(const float* __restrict__ att1) {
    __shared__ float s_att[256];
    int t = threadIdx.x;
    s_att[t] = att1[t];
    __syncthreads();
    int p = blockIdx.x * 8 + (t >> 5);
    if (p >= ET) return;
    int lane = t & 31;
    int s = g_csr_src[p], d = g_csr_dst[p];
    const float* xl = g_xl1 + (size_t)s * 256;
    const float* xr = g_xr1 + (size_t)d * 256;
    float acc[8];
#pragma unroll
    for (int h = 0; h < 8; h++) {
        float v = xl[h * 32 + lane] + xr[h * 32 + lane];
        v = v > 0.f ? v : 0.2f * v;
        acc[h] = v * s_att[h * 32 + lane];
    }
#pragma unroll
    for (int h = 0; h < 8; h++)
#pragma unroll
        for (int o = 16; o; o >>= 1) acc[h] += __shfl_xor_sync(0xFFFFFFFFu, acc[h], o);
    if (lane < 8) {
        float out = acc[0];
#pragma unroll
        for (int h = 1; h < 8; h++) if (lane == h) out = acc[h];
        g_alpha1[(size_t)p * 8 + lane] = out;
    }
}

// ---------------- layer-1 online softmax + aggregate + b1 + ELU --------------
__global__ void k_agg1(const float* __restrict__ b1) {
    __shared__ float s_b[256];
    int t = threadIdx.x;
    s_b[t] = b1[t];
    __syncthreads();

    int node = blockIdx.x * 8 + (t >> 5);
    if (node >= NN) return;
    int lane = t & 31;
    int p0 = g_start[node], p1 = g_start[node + 1];

    float m[8], den[8], acc[8];
#pragma unroll
    for (int h = 0; h < 8; h++) { m[h] = -1e30f; den[h] = 0.f; acc[h] = 0.f; }

    for (int p = p0; p < p1; p++) {
        int s = g_csr_src[p];
        // broadcast loads of the 8 per-head scores
        float4 A0 = *(const float4*)(g_alpha1 + (size_t)p * 8);
        float4 A1 = *(const float4*)(g_alpha1 + (size_t)p * 8 + 4);
        float sc[8] = {A0.x, A0.y, A0.z, A0.w, A1.x, A1.y, A1.z, A1.w};
        const float* xlrow = g_xl1 + (size_t)s * 256;
        float xl[8];
#pragma unroll
        for (int h = 0; h < 8; h++) xl[h] = xlrow[h * 32 + lane];
#pragma unroll
        for (int h = 0; h < 8; h++) {
            if (sc[h] <= m[h]) {
                float w = __expf(sc[h] - m[h]);
                den[h] += w;
                acc[h] += w * xl[h];
            } else {
                float scale = __expf(m[h] - sc[h]);
                den[h] = den[h] * scale + 1.f;
                acc[h] = acc[h] * scale + xl[h];
                m[h] = sc[h];
            }
        }
    }
#pragma unroll
    for (int h = 0; h < 8; h++) {
        float v = acc[h] / (den[h] + 1e-16f) + s_b[h * 32 + lane];
        g_out1[(size_t)node * 256 + h * 32 + lane] = v > 0.f ? v : expm1f(v);
    }
}

// ---------------- GEMM2: h[NN,256] @ [W2l | W2r][256,32] --------------------
__global__ void k_gemm2(const float* __restrict__ Wl, const float* __restrict__ Wr) {
    __shared__ float ws[256 * 32];
    __shared__ float hs[16][256];
    int tid = threadIdx.x;
    for (int i = tid; i < 256 * 32; i += 256) {
        int k = i >> 5, c = i & 31;
        ws[i] = (c < 16) ? Wl[k * 16 + c] : Wr[k * 16 + c - 16];
    }
    int node0 = blockIdx.x * 16;
    for (int i = tid; i < 16 * 256; i += 256) {
        int m = i >> 8, k = i & 255;
        int node = node0 + m;
        hs[m][k] = (node < NN) ? g_out1[(size_t)node * 256 + k] : 0.f;
    }
    __syncthreads();
    int c = tid & 31;
#pragma unroll
    for (int half = 0; half < 2; half++) {
        int m = (tid >> 5) + half * 8;
        int node = node0 + m;
        if (node < NN) {
            float sacc = 0.f;
#pragma unroll 8
            for (int k = 0; k < 256; k++) sacc += hs[m][k] * ws[k * 32 + c];
            if (c < 16) g_xl2[node * 16 + c] = sacc;
            else        g_xr2[node * 16 + c - 16] = sacc;
        }
    }
}

// ---------------- layer-2 fused: score + online softmax + agg + bias + leaky -
__global__ void k_fused2(const float* __restrict__ att2, const float* __restrict__ b2,
                         float* __restrict__ dout) {
    int t = threadIdx.x;
    int node = blockIdx.x * 8 + (t >> 5);
    if (node >= NN) return;
    int lane = t & 31;
    int c = lane & 15;
    int p0 = g_start[node], p1 = g_start[node + 1];

    float xr = g_xr2[node * 16 + c];
    float at = att2[c];
    float m = -1e30f, den = 0.f, acc = 0.f;

    for (int p = p0; p < p1; p++) {
        int s = g_csr_src[p];
        float xl = g_xl2[s * 16 + c];
        float v = xl + xr;
        v = v > 0.f ? v : 0.2f * v;
        float sc = v * at;
#pragma unroll
        for (int o = 8; o; o >>= 1) sc += __shfl_xor_sync(0xFFFFFFFFu, sc, o);
        if (sc <= m) {
            float w = __expf(sc - m);
            den += w;
            acc += w * xl;
        } else {
            float scale = __expf(m - sc);
            den = den * scale + 1.f;
            acc = acc * scale + xl;
            m = sc;
        }
    }
    if (lane < 16) {
        float v = acc / (den + 1e-16f) + b2[c];
        dout[node * 16 + c] = v >= 0.f ? v : 0.01f * v;
    }
}

// ---------------- launch ------------------------------------------------------
extern "C" void kernel_launch(void* const* d_in, const int* in_sizes, int n_in,
                              void* d_out, int out_size) {
    const float* x    = (const float*)d_in[0];
    const int*   ei   = (const int*)d_in[1];
    const float* W1l  = (const float*)d_in[2];
    const float* W1r  = (const float*)d_in[3];
    const float* att1 = (const float*)d_in[4];
    const float* b1   = (const float*)d_in[5];
    const float* W2l  = (const float*)d_in[6];
    const float* W2r  = (const float*)d_in[7];
    const float* att2 = (const float*)d_in[8];
    const float* b2   = (const float*)d_in[9];
    float* out = (float*)d_out;

    k_init<<<(NN + 255) / 256, 256>>>();
    k_hist<<<(ET + 255) / 256, 256>>>(ei);
    k_scan<<<1, 1024>>>();
    k_scatter<<<(ET + 255) / 256, 256>>>(ei);

    dim3 g1(4, (NN + 127) / 128);
    k_gemm1<<<g1, 256>>>(x, W1l, W1r);

    k_score1<<<(ET + 7) / 8, 256>>>(att1);
    k_agg1<<<(NN + 7) / 8, 256>>>(b1);

    k_gemm2<<<(NN + 15) / 16, 256>>>(W2l, W2r);

    k_fused2<<<(NN + 7) / 8, 256>>>(att2, b2, out);
}

// round 5
// speedup vs baseline: 5.5396x; 1.3136x over previous
#include <cuda_runtime.h>
#include <math.h>
#include <stdint.h>

#define NN 50000
#define EE 640000
#define ET 690000   // EE + NN self loops

// ---------------- scratch (device globals) ----------------------------------
__device__ float g_xl1[(size_t)NN * 256];
__device__ float g_xr1[(size_t)NN * 256];
__device__ float g_out1[(size_t)NN * 256];
__device__ float g_alpha1[(size_t)ET * 8];
__device__ float g_maxv[NN * 8];
__device__ float g_xl2[NN * 16];
__device__ float g_xr2[NN * 16];
__device__ int   g_deg[NN];
__device__ int   g_start[NN + 1];
__device__ int   g_cursor[NN];
__device__ int   g_csr_src[ET];
__device__ int   g_csr_dst[ET];

// ---------------- CSR construction ------------------------------------------
__global__ void k_init() {
    int i = blockIdx.x * 256 + threadIdx.x;
    if (i < NN) { g_deg[i] = 0; g_cursor[i] = 0; }
}

__global__ void k_hist(const int* __restrict__ ei) {
    int e = blockIdx.x * 256 + threadIdx.x;
    if (e >= ET) return;
    int d = (e < EE) ? ei[EE + e] : e - EE;
    atomicAdd(&g_deg[d], 1);
}

__global__ void k_scan() {
    __shared__ int sums[1024];
    int t = threadIdx.x;
    const int C = 49;                 // 49*1024 = 50176 >= NN
    int base = t * C;
    int s = 0;
    for (int i = 0; i < C; i++) { int idx = base + i; if (idx < NN) s += g_deg[idx]; }
    sums[t] = s;
    __syncthreads();
    for (int off = 1; off < 1024; off <<= 1) {
        int v = 0;
        if (t >= off) v = sums[t - off];
        __syncthreads();
        sums[t] += v;
        __syncthreads();
    }
    int run = (t == 0) ? 0 : sums[t - 1];
    for (int i = 0; i < C; i++) {
        int idx = base + i;
        if (idx < NN) { g_start[idx] = run; run += g_deg[idx]; }
    }
    if (t == 1023) g_start[NN] = ET;
}

__global__ void k_scatter(const int* __restrict__ ei) {
    int e = blockIdx.x * 256 + threadIdx.x;
    if (e >= ET) return;
    int s = (e < EE) ? ei[e] : e - EE;
    int d = (e < EE) ? ei[EE + e] : e - EE;
    int p = g_start[d] + atomicAdd(&g_cursor[d], 1);
    g_csr_src[p] = s;
    g_csr_dst[p] = d;
}

// ---------------- tf32 helpers ------------------------------------------------
__device__ __forceinline__ float tf32r(float x) {
    uint32_t o;
    asm("cvt.rna.tf32.f32 %0, %1;" : "=r"(o) : "f"(x));
    return __uint_as_float(o);
}

__device__ __forceinline__ void mma_tf32(float c[4], const uint32_t a[4], const uint32_t b[2]) {
    asm volatile(
        "mma.sync.aligned.m16n8k8.row.col.f32.tf32.tf32.f32 "
        "{%0,%1,%2,%3},{%4,%5,%6,%7},{%8,%9},{%0,%1,%2,%3};"
        : "+f"(c[0]), "+f"(c[1]), "+f"(c[2]), "+f"(c[3])
        : "r"(a[0]), "r"(a[1]), "r"(a[2]), "r"(a[3]), "r"(b[0]), "r"(b[1]));
}

// ---------------- GEMM1 (tf32 tensor core): X[NN,128] @ [W1l|W1r][128,512] ---
#define LDA 137
#define LDB 136
__global__ void __launch_bounds__(256, 2) k_gemm1(const float* __restrict__ X,
                                                  const float* __restrict__ Wl,
                                                  const float* __restrict__ Wr) {
    __shared__ float As[32 * LDA];
    __shared__ float Bs[32 * LDB];
    const int bm = blockIdx.y * 128;
    const int bn = blockIdx.x * 128;
    const float* Bsrc = (bn < 256) ? Wl : Wr;
    const int bnl = bn & 255;

    const int tid = threadIdx.x;
    const int wid = tid >> 5, lane = tid & 31;
    const int wm = wid >> 2, wn = wid & 3;
    const int g = lane >> 2, tg = lane & 3;

    float acc[4][4][4];
#pragma unroll
    for (int mt = 0; mt < 4; mt++)
#pragma unroll
        for (int nt = 0; nt < 4; nt++)
#pragma unroll
            for (int r = 0; r < 4; r++) acc[mt][nt][r] = 0.f;

    for (int k0 = 0; k0 < 128; k0 += 32) {
#pragma unroll
        for (int it = 0; it < 4; it++) {
            int idx = tid + it * 256;
            int m = idx >> 3, kq = (idx & 7) * 4;
            float4 v = make_float4(0.f, 0.f, 0.f, 0.f);
            int row = bm + m;
            if (row < NN) v = *(const float4*)(X + (size_t)row * 128 + k0 + kq);
            As[(kq + 0) * LDA + m] = tf32r(v.x);
            As[(kq + 1) * LDA + m] = tf32r(v.y);
            As[(kq + 2) * LDA + m] = tf32r(v.z);
            As[(kq + 3) * LDA + m] = tf32r(v.w);
        }
#pragma unroll
        for (int it = 0; it < 4; it++) {
            int idx = tid + it * 256;
            int k = idx >> 5, nf = (idx & 31) * 4;
            float4 v = *(const float4*)(Bsrc + (size_t)(k0 + k) * 256 + bnl + nf);
            Bs[k * LDB + nf + 0] = tf32r(v.x);
            Bs[k * LDB + nf + 1] = tf32r(v.y);
            Bs[k * LDB + nf + 2] = tf32r(v.z);
            Bs[k * LDB + nf + 3] = tf32r(v.w);
        }
        __syncthreads();

#pragma unroll
        for (int ks = 0; ks < 4; ks++) {
            int kk = ks * 8;
            uint32_t a[4][4], b[4][2];
#pragma unroll
            for (int mt = 0; mt < 4; mt++) {
                int rb = wm * 64 + mt * 16 + g;
                a[mt][0] = __float_as_uint(As[(kk + tg) * LDA + rb]);
                a[mt][1] = __float_as_uint(As[(kk + tg) * LDA + rb + 8]);
                a[mt][2] = __float_as_uint(As[(kk + tg + 4) * LDA + rb]);
                a[mt][3] = __float_as_uint(As[(kk + tg + 4) * LDA + rb + 8]);
            }
#pragma unroll
            for (int nt = 0; nt < 4; nt++) {
                int cb = wn * 32 + nt * 8 + g;
                b[nt][0] = __float_as_uint(Bs[(kk + tg) * LDB + cb]);
                b[nt][1] = __float_as_uint(Bs[(kk + tg + 4) * LDB + cb]);
            }
#pragma unroll
            for (int mt = 0; mt < 4; mt++)
#pragma unroll
                for (int nt = 0; nt < 4; nt++)
                    mma_tf32(acc[mt][nt], a[mt], b[nt]);
        }
        __syncthreads();
    }

    float* dst = (bn < 256) ? g_xl1 : g_xr1;
#pragma unroll
    for (int mt = 0; mt < 4; mt++) {
        int row0 = bm + wm * 64 + mt * 16 + g;
#pragma unroll
        for (int nt = 0; nt < 4; nt++) {
            int col = bnl + wn * 32 + nt * 8 + 2 * tg;
            if (row0 < NN)
                *(float2*)(dst + (size_t)row0 * 256 + col) =
                    make_float2(acc[mt][nt][0], acc[mt][nt][1]);
            if (row0 + 8 < NN)
                *(float2*)(dst + (size_t)(row0 + 8) * 256 + col) =
                    make_float2(acc[mt][nt][2], acc[mt][nt][3]);
        }
    }
}

// ---------------- layer-1 edge scoring (warp per 4 edges, 4 lanes/head) ------
#define EPW 4   // edges per warp
__global__ void k_score1(const float* __restrict__ att1) {
    int t = threadIdx.x;
    int lane = t & 31, h = lane >> 2, q = lane & 3;
    int base = h * 32 + q * 8;
    float4 at0 = *(const float4*)(att1 + base);
    float4 at1 = *(const float4*)(att1 + base + 4);
    int pbase = (blockIdx.x * 8 + (t >> 5)) * EPW;
#pragma unroll
    for (int i = 0; i < EPW; i++) {
        int p = pbase + i;
        if (p >= ET) return;
        int s = g_csr_src[p], d = g_csr_dst[p];
        const float* xl = g_xl1 + (size_t)s * 256 + base;
        const float* xr = g_xr1 + (size_t)d * 256 + base;
        float4 l0 = *(const float4*)(xl);
        float4 l1 = *(const float4*)(xl + 4);
        float4 r0 = *(const float4*)(xr);
        float4 r1 = *(const float4*)(xr + 4);
        float v, acc = 0.f;
        v = l0.x + r0.x; v = v > 0.f ? v : 0.2f * v; acc += at0.x * v;
        v = l0.y + r0.y; v = v > 0.f ? v : 0.2f * v; acc += at0.y * v;
        v = l0.z + r0.z; v = v > 0.f ? v : 0.2f * v; acc += at0.z * v;
        v = l0.w + r0.w; v = v > 0.f ? v : 0.2f * v; acc += at0.w * v;
        v = l1.x + r1.x; v = v > 0.f ? v : 0.2f * v; acc += at1.x * v;
        v = l1.y + r1.y; v = v > 0.f ? v : 0.2f * v; acc += at1.y * v;
        v = l1.z + r1.z; v = v > 0.f ? v : 0.2f * v; acc += at1.z * v;
        v = l1.w + r1.w; v = v > 0.f ? v : 0.2f * v; acc += at1.w * v;
        acc += __shfl_xor_sync(0xFFFFFFFFu, acc, 1);
        acc += __shfl_xor_sync(0xFFFFFFFFu, acc, 2);
        if (q == 0) g_alpha1[(size_t)p * 8 + h] = acc;
    }
}

// ---------------- layer-1 per-node per-head max -------------------------------
__global__ void k_max1() {
    int t = threadIdx.x;
    int node = blockIdx.x * 8 + (t >> 5);
    if (node >= NN) return;
    int lane = t & 31;
    int q = lane >> 3, h = lane & 7;      // q: which p within group of 4
    int p0 = g_start[node], p1 = g_start[node + 1];
    float m = -1e30f;
    for (int p = p0 + q; p < p1; p += 4)
        m = fmaxf(m, g_alpha1[(size_t)p * 8 + h]);
    m = fmaxf(m, __shfl_xor_sync(0xFFFFFFFFu, m, 8));
    m = fmaxf(m, __shfl_xor_sync(0xFFFFFFFFu, m, 16));
    if (lane < 8) g_maxv[node * 8 + h] = m;
}

// ---------------- layer-1 aggregation (warp/node, 4 lanes/head) + b1 + ELU ---
__global__ void k_agg1(const float* __restrict__ b1) {
    int t = threadIdx.x;
    int node = blockIdx.x * 8 + (t >> 5);
    if (node >= NN) return;
    int lane = t & 31, h = lane >> 2, q = lane & 3;
    int base = h * 32 + q * 8;
    int p0 = g_start[node], p1 = g_start[node + 1];
    float m = g_maxv[node * 8 + h];
    float den = 0.f;
    float acc[8];
#pragma unroll
    for (int i = 0; i < 8; i++) acc[i] = 0.f;

    for (int p = p0; p < p1; p++) {
        int s = g_csr_src[p];
        float a = g_alpha1[(size_t)p * 8 + h];
        float w = __expf(a - m);
        den += w;
        const float* xl = g_xl1 + (size_t)s * 256 + base;
        float4 x0 = *(const float4*)(xl);
        float4 x1 = *(const float4*)(xl + 4);
        acc[0] += w * x0.x; acc[1] += w * x0.y;
        acc[2] += w * x0.z; acc[3] += w * x0.w;
        acc[4] += w * x1.x; acc[5] += w * x1.y;
        acc[6] += w * x1.z; acc[7] += w * x1.w;
    }
    float inv = 1.f / (den + 1e-16f);
    float4 bb0 = *(const float4*)(b1 + base);
    float4 bb1 = *(const float4*)(b1 + base + 4);
    float o[8];
    o[0] = acc[0] * inv + bb0.x; o[1] = acc[1] * inv + bb0.y;
    o[2] = acc[2] * inv + bb0.z; o[3] = acc[3] * inv + bb0.w;
    o[4] = acc[4] * inv + bb1.x; o[5] = acc[5] * inv + bb1.y;
    o[6] = acc[6] * inv + bb1.z; o[7] = acc[7] * inv + bb1.w;
#pragma unroll
    for (int i = 0; i < 8; i++) o[i] = o[i] > 0.f ? o[i] : expm1f(o[i]);
    float* dst = g_out1 + (size_t)node * 256 + base;
    *(float4*)(dst)     = make_float4(o[0], o[1], o[2], o[3]);
    *(float4*)(dst + 4) = make_float4(o[4], o[5], o[6], o[7]);
}

// ---------------- GEMM2: h[NN,256] @ [W2l | W2r][256,32] --------------------
__global__ void k_gemm2(const float* __restrict__ Wl, const float* __restrict__ Wr) {
    __shared__ float ws[256 * 32];
    __shared__ float hs[16][256];
    int tid = threadIdx.x;
    for (int i = tid; i < 256 * 32; i += 256) {
        int k = i >> 5, c = i & 31;
        ws[i] = (c < 16) ? Wl[k * 16 + c] : Wr[k * 16 + c - 16];
    }
    int node0 = blockIdx.x * 16;
    for (int i = tid; i < 16 * 256; i += 256) {
        int m = i >> 8, k = i & 255;
        int node = node0 + m;
        hs[m][k] = (node < NN) ? g_out1[(size_t)node * 256 + k] : 0.f;
    }
    __syncthreads();
    int c = tid & 31;
#pragma unroll
    for (int half = 0; half < 2; half++) {
        int m = (tid >> 5) + half * 8;
        int node = node0 + m;
        if (node < NN) {
            float sacc = 0.f;
#pragma unroll 8
            for (int k = 0; k < 256; k++) sacc += hs[m][k] * ws[k * 32 + c];
            if (c < 16) g_xl2[node * 16 + c] = sacc;
            else        g_xr2[node * 16 + c - 16] = sacc;
        }
    }
}

// ---------------- layer-2 fused: score + online softmax + agg + bias + leaky -
__global__ void k_fused2(const float* __restrict__ att2, const float* __restrict__ b2,
                         float* __restrict__ dout) {
    int t = threadIdx.x;
    int node = blockIdx.x * 8 + (t >> 5);
    if (node >= NN) return;
    int lane = t & 31;
    int c = lane & 15;
    int p0 = g_start[node], p1 = g_start[node + 1];

    float xr = g_xr2[node * 16 + c];
    float at = att2[c];
    float m = -1e30f, den = 0.f, acc = 0.f;

    for (int p = p0; p < p1; p++) {
        int s = g_csr_src[p];
        float xl = g_xl2[s * 16 + c];
        float v = xl + xr;
        v = v > 0.f ? v : 0.2f * v;
        float sc = v * at;
#pragma unroll
        for (int o = 8; o; o >>= 1) sc += __shfl_xor_sync(0xFFFFFFFFu, sc, o);
        if (sc <= m) {
            float w = __expf(sc - m);
            den += w;
            acc += w * xl;
        } else {
            float scale = __expf(m - sc);
            den = den * scale + 1.f;
            acc = acc * scale + xl;
            m = sc;
        }
    }
    if (lane < 16) {
        float v = acc / (den + 1e-16f) + b2[c];
        dout[node * 16 + c] = v >= 0.f ? v : 0.01f * v;
    }
}

// ---------------- launch ------------------------------------------------------
extern "C" void kernel_launch(void* const* d_in, const int* in_sizes, int n_in,
                              void* d_out, int out_size) {
    const float* x    = (const float*)d_in[0];
    const int*   ei   = (const int*)d_in[1];
    const float* W1l  = (const float*)d_in[2];
    const float* W1r  = (const float*)d_in[3];
    const float* att1 = (const float*)d_in[4];
    const float* b1   = (const float*)d_in[5];
    const float* W2l  = (const float*)d_in[6];
    const float* W2r  = (const float*)d_in[7];
    const float* att2 = (const float*)d_in[8];
    const float* b2   = (const float*)d_in[9];
    float* out = (float*)d_out;

    k_init<<<(NN + 255) / 256, 256>>>();
    k_hist<<<(ET + 255) / 256, 256>>>(ei);
    k_scan<<<1, 1024>>>();
    k_scatter<<<(ET + 255) / 256, 256>>>(ei);

    dim3 g1(4, (NN + 127) / 128);
    k_gemm1<<<g1, 256>>>(x, W1l, W1r);

    k_score1<<<(ET + 8 * EPW - 1) / (8 * EPW), 256>>>(att1);
    k_max1<<<(NN + 7) / 8, 256>>>();
    k_agg1<<<(NN + 7) / 8, 256>>>(b1);

    k_gemm2<<<(NN + 15) / 16, 256>>>(W2l, W2r);

    k_fused2<<<(NN + 7) / 8, 256>>>(att2, b2, out);
}

// round 6
// speedup vs baseline: 6.7955x; 1.2267x over previous
#include <cuda_runtime.h>
#include <math.h>
#include <stdint.h>

#define NN 50000
#define EE 640000
#define ET 690000   // EE + NN self loops

// ---------------- scratch (device globals) ----------------------------------
__device__ float g_xl1[(size_t)NN * 256];
__device__ float g_xr1[(size_t)NN * 256];
__device__ float g_out1[(size_t)NN * 256];
__device__ float g_xl2[NN * 16];
__device__ float g_xr2[NN * 16];
__device__ int   g_deg[NN];
__device__ int   g_start[NN + 1];
__device__ int   g_cursor[NN];
__device__ int   g_csr_src[ET];

// ---------------- CSR construction ------------------------------------------
__global__ void k_init() {
    int i = blockIdx.x * 256 + threadIdx.x;
    if (i < NN) { g_deg[i] = 0; g_cursor[i] = 0; }
}

__global__ void k_hist(const int* __restrict__ ei) {
    int e = blockIdx.x * 256 + threadIdx.x;
    if (e >= ET) return;
    int d = (e < EE) ? ei[EE + e] : e - EE;
    atomicAdd(&g_deg[d], 1);
}

__global__ void k_scan() {
    __shared__ int sums[1024];
    int t = threadIdx.x;
    const int C = 49;                 // 49*1024 = 50176 >= NN
    int base = t * C;
    int s = 0;
    for (int i = 0; i < C; i++) { int idx = base + i; if (idx < NN) s += g_deg[idx]; }
    sums[t] = s;
    __syncthreads();
    for (int off = 1; off < 1024; off <<= 1) {
        int v = 0;
        if (t >= off) v = sums[t - off];
        __syncthreads();
        sums[t] += v;
        __syncthreads();
    }
    int run = (t == 0) ? 0 : sums[t - 1];
    for (int i = 0; i < C; i++) {
        int idx = base + i;
        if (idx < NN) { g_start[idx] = run; run += g_deg[idx]; }
    }
    if (t == 1023) g_start[NN] = ET;
}

__global__ void k_scatter(const int* __restrict__ ei) {
    int e = blockIdx.x * 256 + threadIdx.x;
    if (e >= ET) return;
    int s = (e < EE) ? ei[e] : e - EE;
    int d = (e < EE) ? ei[EE + e] : e - EE;
    int p = g_start[d] + atomicAdd(&g_cursor[d], 1);
    g_csr_src[p] = s;
}

// ---------------- tf32 helpers ------------------------------------------------
__device__ __forceinline__ float tf32r(float x) {
    uint32_t o;
    asm("cvt.rna.tf32.f32 %0, %1;" : "=r"(o) : "f"(x));
    return __uint_as_float(o);
}

__device__ __forceinline__ void mma_tf32(float c[4], const uint32_t a[4], const uint32_t b[2]) {
    asm volatile(
        "mma.sync.aligned.m16n8k8.row.col.f32.tf32.tf32.f32 "
        "{%0,%1,%2,%3},{%4,%5,%6,%7},{%8,%9},{%0,%1,%2,%3};"
        : "+f"(c[0]), "+f"(c[1]), "+f"(c[2]), "+f"(c[3])
        : "r"(a[0]), "r"(a[1]), "r"(a[2]), "r"(a[3]), "r"(b[0]), "r"(b[1]));
}

// ---------------- GEMM1 (tf32 tensor core): X[NN,128] @ [W1l|W1r][128,512] ---
#define LDA 137
#define LDB 136
__global__ void __launch_bounds__(256, 2) k_gemm1(const float* __restrict__ X,
                                                  const float* __restrict__ Wl,
                                                  const float* __restrict__ Wr) {
    __shared__ float As[32 * LDA];
    __shared__ float Bs[32 * LDB];
    const int bm = blockIdx.y * 128;
    const int bn = blockIdx.x * 128;
    const float* Bsrc = (bn < 256) ? Wl : Wr;
    const int bnl = bn & 255;

    const int tid = threadIdx.x;
    const int wid = tid >> 5, lane = tid & 31;
    const int wm = wid >> 2, wn = wid & 3;
    const int g = lane >> 2, tg = lane & 3;

    float acc[4][4][4];
#pragma unroll
    for (int mt = 0; mt < 4; mt++)
#pragma unroll
        for (int nt = 0; nt < 4; nt++)
#pragma unroll
            for (int r = 0; r < 4; r++) acc[mt][nt][r] = 0.f;

    for (int k0 = 0; k0 < 128; k0 += 32) {
#pragma unroll
        for (int it = 0; it < 4; it++) {
            int idx = tid + it * 256;
            int m = idx >> 3, kq = (idx & 7) * 4;
            float4 v = make_float4(0.f, 0.f, 0.f, 0.f);
            int row = bm + m;
            if (row < NN) v = *(const float4*)(X + (size_t)row * 128 + k0 + kq);
            As[(kq + 0) * LDA + m] = tf32r(v.x);
            As[(kq + 1) * LDA + m] = tf32r(v.y);
            As[(kq + 2) * LDA + m] = tf32r(v.z);
            As[(kq + 3) * LDA + m] = tf32r(v.w);
        }
#pragma unroll
        for (int it = 0; it < 4; it++) {
            int idx = tid + it * 256;
            int k = idx >> 5, nf = (idx & 31) * 4;
            float4 v = *(const float4*)(Bsrc + (size_t)(k0 + k) * 256 + bnl + nf);
            Bs[k * LDB + nf + 0] = tf32r(v.x);
            Bs[k * LDB + nf + 1] = tf32r(v.y);
            Bs[k * LDB + nf + 2] = tf32r(v.z);
            Bs[k * LDB + nf + 3] = tf32r(v.w);
        }
        __syncthreads();

#pragma unroll
        for (int ks = 0; ks < 4; ks++) {
            int kk = ks * 8;
            uint32_t a[4][4], b[4][2];
#pragma unroll
            for (int mt = 0; mt < 4; mt++) {
                int rb = wm * 64 + mt * 16 + g;
                a[mt][0] = __float_as_uint(As[(kk + tg) * LDA + rb]);
                a[mt][1] = __float_as_uint(As[(kk + tg) * LDA + rb + 8]);
                a[mt][2] = __float_as_uint(As[(kk + tg + 4) * LDA + rb]);
                a[mt][3] = __float_as_uint(As[(kk + tg + 4) * LDA + rb + 8]);
            }
#pragma unroll
            for (int nt = 0; nt < 4; nt++) {
                int cb = wn * 32 + nt * 8 + g;
                b[nt][0] = __float_as_uint(Bs[(kk + tg) * LDB + cb]);
                b[nt][1] = __float_as_uint(Bs[(kk + tg + 4) * LDB + cb]);
            }
#pragma unroll
            for (int mt = 0; mt < 4; mt++)
#pragma unroll
                for (int nt = 0; nt < 4; nt++)
                    mma_tf32(acc[mt][nt], a[mt], b[nt]);
        }
        __syncthreads();
    }

    float* dst = (bn < 256) ? g_xl1 : g_xr1;
#pragma unroll
    for (int mt = 0; mt < 4; mt++) {
        int row0 = bm + wm * 64 + mt * 16 + g;
#pragma unroll
        for (int nt = 0; nt < 4; nt++) {
            int col = bnl + wn * 32 + nt * 8 + 2 * tg;
            if (row0 < NN)
                *(float2*)(dst + (size_t)row0 * 256 + col) =
                    make_float2(acc[mt][nt][0], acc[mt][nt][1]);
            if (row0 + 8 < NN)
                *(float2*)(dst + (size_t)(row0 + 8) * 256 + col) =
                    make_float2(acc[mt][nt][2], acc[mt][nt][3]);
        }
    }
}

// ---- layer-1 fused: score + online softmax + aggregate + b1 + ELU -----------
// warp per node; lane = h*4+q owns 8 contiguous floats of head h.
__global__ void k_fused1(const float* __restrict__ att1, const float* __restrict__ b1) {
    int t = threadIdx.x;
    int node = blockIdx.x * 8 + (t >> 5);
    if (node >= NN) return;
    int lane = t & 31, h = lane >> 2, q = lane & 3;
    int base = h * 32 + q * 8;
    int p0 = g_start[node], p1 = g_start[node + 1];

    float4 at0 = *(const float4*)(att1 + base);
    float4 at1 = *(const float4*)(att1 + base + 4);
    const float* xrp = g_xr1 + (size_t)node * 256 + base;
    float4 xr0 = *(const float4*)(xrp);
    float4 xr1 = *(const float4*)(xrp + 4);

    float m = -1e30f, den = 0.f;
    float acc[8];
#pragma unroll
    for (int i = 0; i < 8; i++) acc[i] = 0.f;

    for (int p = p0; p < p1; p++) {
        int s = g_csr_src[p];
        const float* xlp = g_xl1 + (size_t)s * 256 + base;
        float4 l0 = *(const float4*)(xlp);
        float4 l1 = *(const float4*)(xlp + 4);

        float v, sc = 0.f;
        v = l0.x + xr0.x; v = v > 0.f ? v : 0.2f * v; sc += at0.x * v;
        v = l0.y + xr0.y; v = v > 0.f ? v : 0.2f * v; sc += at0.y * v;
        v = l0.z + xr0.z; v = v > 0.f ? v : 0.2f * v; sc += at0.z * v;
        v = l0.w + xr0.w; v = v > 0.f ? v : 0.2f * v; sc += at0.w * v;
        v = l1.x + xr1.x; v = v > 0.f ? v : 0.2f * v; sc += at1.x * v;
        v = l1.y + xr1.y; v = v > 0.f ? v : 0.2f * v; sc += at1.y * v;
        v = l1.z + xr1.z; v = v > 0.f ? v : 0.2f * v; sc += at1.z * v;
        v = l1.w + xr1.w; v = v > 0.f ? v : 0.2f * v; sc += at1.w * v;
        sc += __shfl_xor_sync(0xFFFFFFFFu, sc, 1);
        sc += __shfl_xor_sync(0xFFFFFFFFu, sc, 2);

        if (sc <= m) {
            float w = __expf(sc - m);
            den += w;
            acc[0] += w * l0.x; acc[1] += w * l0.y; acc[2] += w * l0.z; acc[3] += w * l0.w;
            acc[4] += w * l1.x; acc[5] += w * l1.y; acc[6] += w * l1.z; acc[7] += w * l1.w;
        } else {
            float sfac = __expf(m - sc);
            den = den * sfac + 1.f;
            acc[0] = acc[0] * sfac + l0.x; acc[1] = acc[1] * sfac + l0.y;
            acc[2] = acc[2] * sfac + l0.z; acc[3] = acc[3] * sfac + l0.w;
            acc[4] = acc[4] * sfac + l1.x; acc[5] = acc[5] * sfac + l1.y;
            acc[6] = acc[6] * sfac + l1.z; acc[7] = acc[7] * sfac + l1.w;
            m = sc;
        }
    }

    float inv = 1.f / (den + 1e-16f);
    float4 bb0 = *(const float4*)(b1 + base);
    float4 bb1 = *(const float4*)(b1 + base + 4);
    float o[8];
    o[0] = acc[0] * inv + bb0.x; o[1] = acc[1] * inv + bb0.y;
    o[2] = acc[2] * inv + bb0.z; o[3] = acc[3] * inv + bb0.w;
    o[4] = acc[4] * inv + bb1.x; o[5] = acc[5] * inv + bb1.y;
    o[6] = acc[6] * inv + bb1.z; o[7] = acc[7] * inv + bb1.w;
#pragma unroll
    for (int i = 0; i < 8; i++) o[i] = o[i] > 0.f ? o[i] : expm1f(o[i]);
    float* dst = g_out1 + (size_t)node * 256 + base;
    *(float4*)(dst)     = make_float4(o[0], o[1], o[2], o[3]);
    *(float4*)(dst + 4) = make_float4(o[4], o[5], o[6], o[7]);
}

// ---------------- GEMM2: h[NN,256] @ [W2l | W2r][256,32] --------------------
__global__ void k_gemm2(const float* __restrict__ Wl, const float* __restrict__ Wr) {
    __shared__ float ws[256 * 32];
    __shared__ float hs[16][256];
    int tid = threadIdx.x;
    for (int i = tid; i < 256 * 32; i += 256) {
        int k = i >> 5, c = i & 31;
        ws[i] = (c < 16) ? Wl[k * 16 + c] : Wr[k * 16 + c - 16];
    }
    int node0 = blockIdx.x * 16;
    for (int i = tid; i < 16 * 256; i += 256) {
        int m = i >> 8, k = i & 255;
        int node = node0 + m;
        hs[m][k] = (node < NN) ? g_out1[(size_t)node * 256 + k] : 0.f;
    }
    __syncthreads();
    int c = tid & 31;
#pragma unroll
    for (int half = 0; half < 2; half++) {
        int m = (tid >> 5) + half * 8;
        int node = node0 + m;
        if (node < NN) {
            float sacc = 0.f;
#pragma unroll 8
            for (int k = 0; k < 256; k++) sacc += hs[m][k] * ws[k * 32 + c];
            if (c < 16) g_xl2[node * 16 + c] = sacc;
            else        g_xr2[node * 16 + c - 16] = sacc;
        }
    }
}

// ---------------- layer-2 fused: score + online softmax + agg + bias + leaky -
__global__ void k_fused2(const float* __restrict__ att2, const float* __restrict__ b2,
                         float* __restrict__ dout) {
    int t = threadIdx.x;
    int node = blockIdx.x * 8 + (t >> 5);
    if (node >= NN) return;
    int lane = t & 31;
    int c = lane & 15;
    int p0 = g_start[node], p1 = g_start[node + 1];

    float xr = g_xr2[node * 16 + c];
    float at = att2[c];
    float m = -1e30f, den = 0.f, acc = 0.f;

    for (int p = p0; p < p1; p++) {
        int s = g_csr_src[p];
        float xl = g_xl2[s * 16 + c];
        float v = xl + xr;
        v = v > 0.f ? v : 0.2f * v;
        float sc = v * at;
#pragma unroll
        for (int o = 8; o; o >>= 1) sc += __shfl_xor_sync(0xFFFFFFFFu, sc, o);
        if (sc <= m) {
            float w = __expf(sc - m);
            den += w;
            acc += w * xl;
        } else {
            float sfac = __expf(m - sc);
            den = den * sfac + 1.f;
            acc = acc * sfac + xl;
            m = sc;
        }
    }
    if (lane < 16) {
        float v = acc / (den + 1e-16f) + b2[c];
        dout[node * 16 + c] = v >= 0.f ? v : 0.01f * v;
    }
}

// ---------------- launch ------------------------------------------------------
extern "C" void kernel_launch(void* const* d_in, const int* in_sizes, int n_in,
                              void* d_out, int out_size) {
    const float* x    = (const float*)d_in[0];
    const int*   ei   = (const int*)d_in[1];
    const float* W1l  = (const float*)d_in[2];
    const float* W1r  = (const float*)d_in[3];
    const float* att1 = (const float*)d_in[4];
    const float* b1   = (const float*)d_in[5];
    const float* W2l  = (const float*)d_in[6];
    const float* W2r  = (const float*)d_in[7];
    const float* att2 = (const float*)d_in[8];
    const float* b2   = (const float*)d_in[9];
    float* out = (float*)d_out;

    k_init<<<(NN + 255) / 256, 256>>>();
    k_hist<<<(ET + 255) / 256, 256>>>(ei);
    k_scan<<<1, 1024>>>();
    k_scatter<<<(ET + 255) / 256, 256>>>(ei);

    dim3 g1(4, (NN + 127) / 128);
    k_gemm1<<<g1, 256>>>(x, W1l, W1r);

    k_fused1<<<(NN + 7) / 8, 256>>>(att1, b1);

    k_gemm2<<<(NN + 15) / 16, 256>>>(W2l, W2r);

    k_fused2<<<(NN + 7) / 8, 256>>>(att2, b2, out);
}